// round 16
// baseline (speedup 1.0000x reference)
#include <cuda_runtime.h>
#include <cuda_fp16.h>
#include <math.h>
#include <stdint.h>

// Problem constants: B=4, S=1024, D=1024, H=16, DK=64
#define BB 4
#define SS 1024
#define HH 16
#define KC 1024          // single fp16 slab for both Q and K
#define NEGV -10000000000.0f

// Scratch: Qc/Kc 8MB each (fp16).
__device__ __half g_Qc[(size_t)BB * SS * KC];
__device__ __half g_Kc[(size_t)BB * SS * KC];

__device__ __forceinline__ uint32_t packf2(float a, float b) {
    __half2 h = __floats2half2_rn(a, b);
    return *(uint32_t*)&h;
}

// Fast accurate tanh: 1 - 2/(e^{2x}+1).  __expf rel err ~2^-22; endpoints exact.
__device__ __forceinline__ float tanh_fast(float x) {
    float e2 = __expf(2.0f * x);
    return 1.0f - __fdividef(2.0f, e2 + 1.0f);
}

// ---------------------------------------------------------------------------
// Tensor-core projection, pure fp16 operands (K=64, 4 mma K-steps).
// Grid: 1024 blocks; blocks 0..511 -> Q, 512..1023 -> K.
// Each block: 128 rows of one (b,h) slab.  P = Xhi @ Whi^T (fp32 acc),
// val = tanh(P + bias) * scale, stored fp16.
// ---------------------------------------------------------------------------
#define XS_STRIDE 72
#define PROJ_SMEM ((128 + 64) * XS_STRIDE * 2 + 256)

__global__ void __launch_bounds__(256)
proj_mma_kernel(const float* __restrict__ qin, const float* __restrict__ kin,
                const float* __restrict__ Wq, const float* __restrict__ bq,
                const float* __restrict__ Wk, const float* __restrict__ bk,
                const float* __restrict__ Wc,
                __half* __restrict__ qc, __half* __restrict__ kc)
{
    extern __shared__ __half sp[];
    __half* Xs  = sp;                            // 128 x 72
    __half* Wsm = sp + 128 * XS_STRIDE;          // 64 x 72
    float*  bs  = (float*)(sp + (128 + 64) * XS_STRIDE);

    const bool isQ = blockIdx.x < 512;
    const int bid  = blockIdx.x & 511;
    const int slab = bid >> 3;                   // b*16 + h
    const int bis  = bid & 7;                    // 128-row block within slab
    const int b    = slab >> 4;
    const int h    = slab & 15;

    const float* x    = (isQ ? qin : kin) + ((size_t)slab * 1024 + bis * 128) * 64;
    const float* W    = isQ ? Wq : Wk;
    const float* bias = isQ ? bq : bk;
    __half* out = isQ ? qc : kc;
    const float scale = isQ ? Wc[h] : 1.0f;

    const int t = threadIdx.x;
    if (t < 64) bs[t] = bias[t];

    // Stage X tile (128x64 fp32) -> Xs fp16
    {
        const int r  = t >> 1;
        const int cs = (t & 1) * 32;
        const float4* xg = (const float4*)(x + r * 64 + cs);
        #pragma unroll
        for (int i = 0; i < 8; ++i) {
            float4 v = xg[i];
            uint2 hiv;
            hiv.x = packf2(v.x, v.y);
            hiv.y = packf2(v.z, v.w);
            *(uint2*)&Xs[r * XS_STRIDE + cs + 4 * i] = hiv;
        }
    }
    // Stage W (64x64 fp32) -> Wsm fp16
    {
        const int d   = t >> 2;
        const int seg = (t & 3) * 16;
        const float4* wg = (const float4*)(W + d * 64 + seg);
        #pragma unroll
        for (int i = 0; i < 4; ++i) {
            float4 v = wg[i];
            uint2 hiv;
            hiv.x = packf2(v.x, v.y);
            hiv.y = packf2(v.z, v.w);
            *(uint2*)&Wsm[d * XS_STRIDE + seg + 4 * i] = hiv;
        }
    }
    __syncthreads();

    const int lane = t & 31, warp = t >> 5;
    const int quad = lane >> 3, l7 = lane & 7;
    const uint32_t sX = (uint32_t)__cvta_generic_to_shared(Xs);
    const uint32_t sW = (uint32_t)__cvta_generic_to_shared(Wsm);

    const int aRow = warp * 16 + ((quad & 1) << 3) + l7;
    const int aK   = (quad >> 1) << 3;
    const int bRow = ((quad >> 1) << 3) + l7;
    const int bK   = (quad & 1) << 3;

    float acc[8][4];
    #pragma unroll
    for (int ni = 0; ni < 8; ++ni)
        #pragma unroll
        for (int j = 0; j < 4; ++j) acc[ni][j] = 0.0f;

    #pragma unroll
    for (int ks = 0; ks < 4; ++ks) {
        const int koff = ks * 16;
        uint32_t a0, a1, a2, a3;
        {
            uint32_t addr = sX + (uint32_t)(aRow * XS_STRIDE + koff + aK) * 2;
            asm volatile(
                "ldmatrix.sync.aligned.m8n8.x4.shared.b16 {%0,%1,%2,%3}, [%4];"
                : "=r"(a0), "=r"(a1), "=r"(a2), "=r"(a3) : "r"(addr));
        }
        uint32_t br[8][2];
        #pragma unroll
        for (int p = 0; p < 4; ++p) {
            uint32_t addr = sW +
                (uint32_t)((p * 16 + bRow) * XS_STRIDE + koff + bK) * 2;
            uint32_t r0, r1, r2, r3;
            asm volatile(
                "ldmatrix.sync.aligned.m8n8.x4.shared.b16 {%0,%1,%2,%3}, [%4];"
                : "=r"(r0), "=r"(r1), "=r"(r2), "=r"(r3) : "r"(addr));
            br[2 * p][0]     = r0; br[2 * p][1]     = r1;
            br[2 * p + 1][0] = r2; br[2 * p + 1][1] = r3;
        }
        #pragma unroll
        for (int ni = 0; ni < 8; ++ni)
            asm volatile(
                "mma.sync.aligned.m16n8k16.row.col.f32.f16.f16.f32 "
                "{%0,%1,%2,%3}, {%4,%5,%6,%7}, {%8,%9}, {%0,%1,%2,%3};"
                : "+f"(acc[ni][0]), "+f"(acc[ni][1]),
                  "+f"(acc[ni][2]), "+f"(acc[ni][3])
                : "r"(a0), "r"(a1), "r"(a2), "r"(a3),
                  "r"(br[ni][0]), "r"(br[ni][1]));
    }

    // Epilogue: bias + tanh_fast + scale, fp16 stores
    const int i0 = bis * 128 + warp * 16 + (lane >> 2);   // row within slab
    const int cb = (lane & 3) * 2;
    const size_t base0 = (size_t)((b << 10) + i0)     * KC + h * 64;
    const size_t base1 = (size_t)((b << 10) + i0 + 8) * KC + h * 64;

    #pragma unroll
    for (int ni = 0; ni < 8; ++ni) {
        const int c = ni * 8 + cb;
        const float bv0 = bs[c], bv1 = bs[c + 1];

        float v0 = tanh_fast(acc[ni][0] + bv0) * scale;
        float v1 = tanh_fast(acc[ni][1] + bv1) * scale;
        *(uint32_t*)&out[base0 + c] = packf2(v0, v1);

        float v2 = tanh_fast(acc[ni][2] + bv0) * scale;
        float v3 = tanh_fast(acc[ni][3] + bv1) * scale;
        *(uint32_t*)&out[base1 + c] = packf2(v2, v3);
    }
}

// ---------------------------------------------------------------------------
// fp16 NT GEMM: C[b] = A[b] * B[b]^T, M=N=K=1024, 4 batches.
// 128x128 tile, BK=32, 256 threads, mma.sync m16n8k16, 3-stage cp.async.
// ---------------------------------------------------------------------------
__global__ void __launch_bounds__(256, 2)
gemm_fp16_nt(const __half* __restrict__ A,
             const __half* __restrict__ B,
             float* __restrict__ C)
{
    constexpr int BM = 128, BN = 128, BK = 32, LDS = 40, NSTAGE = 3;
    constexpr int KTILES = KC / BK;              // 32
    extern __shared__ __half sh[];

    const int t    = threadIdx.x;
    const int lane = t & 31;
    const int warp = t >> 5;
    const int wm   = warp & 1;
    const int wn   = warp >> 1;
    const int mW   = wm * 64;
    const int nW   = wn * 32;
    const int quad = lane >> 3;
    const int l7   = lane & 7;

    A += (size_t)blockIdx.z * SS * KC + (size_t)blockIdx.y * BM * KC;
    B += (size_t)blockIdx.z * SS * KC + (size_t)blockIdx.x * BN * KC;
    C += (size_t)blockIdx.z * SS * SS;

    const uint32_t sbase = (uint32_t)__cvta_generic_to_shared(sh);
    const uint32_t stageBytes = (uint32_t)(BM + BN) * LDS * 2;
    const uint32_t bOffBytes  = (uint32_t)BM * LDS * 2;

    const int rS = t >> 2;
    const int cS = (t & 3) * 8;
    const __half* gA0 = A + (size_t)rS * KC + cS;
    const __half* gA1 = A + (size_t)(rS + 64) * KC + cS;
    const __half* gB0 = B + (size_t)rS * KC + cS;
    const __half* gB1 = B + (size_t)(rS + 64) * KC + cS;
    const uint32_t dA0 = (uint32_t)(rS * LDS + cS) * 2;
    const uint32_t dA1 = (uint32_t)((rS + 64) * LDS + cS) * 2;

    #define LOAD_STAGE(kt, s)                                                   \
    do {                                                                        \
        uint32_t sb = sbase + (uint32_t)(s) * stageBytes;                       \
        int ko = (kt) * BK;                                                     \
        asm volatile("cp.async.cg.shared.global [%0], [%1], 16;" ::             \
            "r"(sb + dA0), "l"(gA0 + ko));                                      \
        asm volatile("cp.async.cg.shared.global [%0], [%1], 16;" ::             \
            "r"(sb + dA1), "l"(gA1 + ko));                                      \
        asm volatile("cp.async.cg.shared.global [%0], [%1], 16;" ::             \
            "r"(sb + bOffBytes + dA0), "l"(gB0 + ko));                          \
        asm volatile("cp.async.cg.shared.global [%0], [%1], 16;" ::             \
            "r"(sb + bOffBytes + dA1), "l"(gB1 + ko));                          \
    } while (0)

    float acc[4][4][4];
    #pragma unroll
    for (int mi = 0; mi < 4; ++mi)
        #pragma unroll
        for (int ni = 0; ni < 4; ++ni)
            #pragma unroll
            for (int r = 0; r < 4; ++r) acc[mi][ni][r] = 0.0f;

    const int aRow  = mW + ((quad & 1) << 3) + l7;
    const int aKoff = (quad >> 1) << 3;
    const int bRowQ = ((quad >> 1) << 3) + l7;
    const int bKoff = (quad & 1) << 3;

    LOAD_STAGE(0, 0);
    asm volatile("cp.async.commit_group;");
    LOAD_STAGE(1, 1);
    asm volatile("cp.async.commit_group;");
    asm volatile("cp.async.wait_group 1;");
    __syncthreads();

    for (int kt = 0; kt < KTILES; ++kt) {
        if (kt + 2 < KTILES) {
            LOAD_STAGE(kt + 2, (kt + 2) % NSTAGE);
        }
        asm volatile("cp.async.commit_group;");

        const uint32_t sA = sbase + (uint32_t)(kt % NSTAGE) * stageBytes;
        const uint32_t sB = sA + bOffBytes;

        #pragma unroll
        for (int ks = 0; ks < 2; ++ks) {
            uint32_t ar[4][4];
            #pragma unroll
            for (int mi = 0; mi < 4; ++mi) {
                uint32_t addr = sA +
                    (uint32_t)((aRow + mi * 16) * LDS + ks * 16 + aKoff) * 2;
                asm volatile(
                    "ldmatrix.sync.aligned.m8n8.x4.shared.b16 {%0,%1,%2,%3}, [%4];"
                    : "=r"(ar[mi][0]), "=r"(ar[mi][1]),
                      "=r"(ar[mi][2]), "=r"(ar[mi][3])
                    : "r"(addr));
            }
            uint32_t br[4][2];
            #pragma unroll
            for (int p = 0; p < 2; ++p) {
                uint32_t addr = sB +
                    (uint32_t)((nW + p * 16 + bRowQ) * LDS + ks * 16 + bKoff) * 2;
                uint32_t r0, r1, r2, r3;
                asm volatile(
                    "ldmatrix.sync.aligned.m8n8.x4.shared.b16 {%0,%1,%2,%3}, [%4];"
                    : "=r"(r0), "=r"(r1), "=r"(r2), "=r"(r3)
                    : "r"(addr));
                br[2 * p][0]     = r0; br[2 * p][1]     = r1;
                br[2 * p + 1][0] = r2; br[2 * p + 1][1] = r3;
            }
            #pragma unroll
            for (int mi = 0; mi < 4; ++mi)
                #pragma unroll
                for (int ni = 0; ni < 4; ++ni)
                    asm volatile(
                        "mma.sync.aligned.m16n8k16.row.col.f32.f16.f16.f32 "
                        "{%0,%1,%2,%3}, {%4,%5,%6,%7}, {%8,%9}, {%0,%1,%2,%3};"
                        : "+f"(acc[mi][ni][0]), "+f"(acc[mi][ni][1]),
                          "+f"(acc[mi][ni][2]), "+f"(acc[mi][ni][3])
                        : "r"(ar[mi][0]), "r"(ar[mi][1]),
                          "r"(ar[mi][2]), "r"(ar[mi][3]),
                          "r"(br[ni][0]), "r"(br[ni][1]));
        }

        asm volatile("cp.async.wait_group 1;");
        __syncthreads();
    }

    #pragma unroll
    for (int mi = 0; mi < 4; ++mi) {
        #pragma unroll
        for (int ni = 0; ni < 4; ++ni) {
            int row = blockIdx.y * BM + mW + mi * 16 + (lane >> 2);
            int col = blockIdx.x * BN + nW + ni * 8 + ((lane & 3) << 1);
            float2 v0 = make_float2(acc[mi][ni][0], acc[mi][ni][1]);
            float2 v1 = make_float2(acc[mi][ni][2], acc[mi][ni][3]);
            *(float2*)&C[(size_t)row * SS + col]       = v0;
            *(float2*)&C[(size_t)(row + 8) * SS + col] = v1;
        }
    }
    #undef LOAD_STAGE
}

// ---------------------------------------------------------------------------
// Masked softmax over rows of 1024, in-place on C (= d_out).
// ---------------------------------------------------------------------------
__global__ void __launch_bounds__(256)
softmax_kernel(float* __restrict__ C, const int* __restrict__ mask,
               const float* __restrict__ bcp)
{
    const size_t row = blockIdx.x;
    float* p = C + row * 1024;
    const int* mp = mask + row * 1024;
    const int t = threadIdx.x;
    const float bias = bcp[0];

    float4 v = ((const float4*)p)[t];
    int4  mk = ((const int4*)mp)[t];

    float x0 = mk.x ? v.x + bias : NEGV;
    float x1 = mk.y ? v.y + bias : NEGV;
    float x2 = mk.z ? v.z + bias : NEGV;
    float x3 = mk.w ? v.w + bias : NEGV;

    float mx = fmaxf(fmaxf(x0, x1), fmaxf(x2, x3));
    #pragma unroll
    for (int o = 16; o; o >>= 1)
        mx = fmaxf(mx, __shfl_xor_sync(0xffffffffu, mx, o));

    __shared__ float red_m[8];
    __shared__ float red_s[8];
    if ((t & 31) == 0) red_m[t >> 5] = mx;
    __syncthreads();
    mx = red_m[0];
    #pragma unroll
    for (int i = 1; i < 8; ++i) mx = fmaxf(mx, red_m[i]);

    float e0 = __expf(x0 - mx);
    float e1 = __expf(x1 - mx);
    float e2 = __expf(x2 - mx);
    float e3 = __expf(x3 - mx);
    float s = e0 + e1 + e2 + e3;
    #pragma unroll
    for (int o = 16; o; o >>= 1)
        s += __shfl_xor_sync(0xffffffffu, s, o);
    if ((t & 31) == 0) red_s[t >> 5] = s;
    __syncthreads();
    float tot = red_s[0];
    #pragma unroll
    for (int i = 1; i < 8; ++i) tot += red_s[i];

    const float inv = __fdividef(1.0f, tot);
    v.x = e0 * inv; v.y = e1 * inv; v.z = e2 * inv; v.w = e3 * inv;
    ((float4*)p)[t] = v;
}

// ---------------------------------------------------------------------------
// Launch
// ---------------------------------------------------------------------------
extern "C" void kernel_launch(void* const* d_in, const int* in_sizes, int n_in,
                              void* d_out, int out_size)
{
    const float* query = (const float*)d_in[0];
    const float* key   = (const float*)d_in[1];
    const int*   mask  = (const int*)  d_in[2];
    const float* Wq    = (const float*)d_in[3];
    const float* bq    = (const float*)d_in[4];
    const float* Wk    = (const float*)d_in[5];
    const float* bk    = (const float*)d_in[6];
    const float* Wc    = (const float*)d_in[7];
    const float* bc    = (const float*)d_in[8];
    float* out = (float*)d_out;

    __half *qc, *kc;
    cudaGetSymbolAddress((void**)&qc, g_Qc);
    cudaGetSymbolAddress((void**)&kc, g_Kc);

    const int smemBytes = 3 * (128 + 128) * 40 * 2;   // 61440
    cudaFuncSetAttribute(gemm_fp16_nt,
                         cudaFuncAttributeMaxDynamicSharedMemorySize, smemBytes);
    cudaFuncSetAttribute(proj_mma_kernel,
                         cudaFuncAttributeMaxDynamicSharedMemorySize, PROJ_SMEM);

    // Tensor-core projection (pure fp16): Q and K -> fp16 slabs (stride 1024)
    proj_mma_kernel<<<1024, 256, PROJ_SMEM>>>(query, key, Wq, bq, Wk, bk, Wc,
                                              qc, kc);

    // comb[b] = Qc[b] @ Kc[b]^T  (K=1024)
    gemm_fp16_nt<<<dim3(8, 8, 4), 256, smemBytes>>>(qc, kc, out);

    // mask + softmax, in-place
    softmax_kernel<<<BB * SS, 256>>>(out, mask, bc);
}

// round 17
// speedup vs baseline: 1.2405x; 1.2405x over previous
#include <cuda_runtime.h>
#include <cuda_fp16.h>
#include <math.h>
#include <stdint.h>

// Problem constants: B=4, S=1024, D=1024, H=16, DK=64
#define BB 4
#define SS 1024
#define HH 16
#define KC 1024          // single fp16 slab for both Q and K
#define NEGV -10000000000.0f

// Scratch: Qc/Kc 8MB each (fp16).
__device__ __half g_Qc[(size_t)BB * SS * KC];
__device__ __half g_Kc[(size_t)BB * SS * KC];

__device__ __forceinline__ uint32_t packf2(float a, float b) {
    __half2 h = __floats2half2_rn(a, b);
    return *(uint32_t*)&h;
}

// Fast accurate tanh: 1 - 2/(e^{2x}+1).  __expf rel err ~2^-22; endpoints exact.
__device__ __forceinline__ float tanh_fast(float x) {
    float e2 = __expf(2.0f * x);
    return 1.0f - __fdividef(2.0f, e2 + 1.0f);
}

// ---------------------------------------------------------------------------
// Tensor-core projection, pure fp16 operands (K=64, 4 mma K-steps).
// Grid: 1024 blocks; blocks 0..511 -> Q, 512..1023 -> K.
// Each block: 128 rows of one (b,h) slab.  P = Xhi @ Whi^T (fp32 acc),
// val = tanh(P + bias) * scale, stored fp16.
// I/O fully coalesced: linear float4 staging loads; epilogue bounces results
// through smem then stores 16B vectors (8 threads per 128B output row).
// ---------------------------------------------------------------------------
#define XS_STRIDE 72
#define PROJ_SMEM ((128 + 64) * XS_STRIDE * 2 + 256)

__global__ void __launch_bounds__(256)
proj_mma_kernel(const float* __restrict__ qin, const float* __restrict__ kin,
                const float* __restrict__ Wq, const float* __restrict__ bq,
                const float* __restrict__ Wk, const float* __restrict__ bk,
                const float* __restrict__ Wc,
                __half* __restrict__ qc, __half* __restrict__ kc)
{
    extern __shared__ __half sp[];
    __half* Xs  = sp;                            // 128 x 72 (staging, then results)
    __half* Wsm = sp + 128 * XS_STRIDE;          // 64 x 72
    float*  bs  = (float*)(sp + (128 + 64) * XS_STRIDE);

    const bool isQ = blockIdx.x < 512;
    const int bid  = blockIdx.x & 511;
    const int slab = bid >> 3;                   // b*16 + h
    const int bis  = bid & 7;                    // 128-row block within slab
    const int b    = slab >> 4;
    const int h    = slab & 15;

    const float* x    = (isQ ? qin : kin) + ((size_t)slab * 1024 + bis * 128) * 64;
    const float* W    = isQ ? Wq : Wk;
    const float* bias = isQ ? bq : bk;
    __half* out = isQ ? qc : kc;
    const float scale = isQ ? Wc[h] : 1.0f;

    const int t = threadIdx.x;
    if (t < 64) bs[t] = bias[t];

    // Stage X tile (128x64 fp32) -> Xs fp16.  Linear, fully coalesced LDG.
    {
        const float4* xg = (const float4*)x;     // 2048 float4 = 128 rows x 16
        #pragma unroll
        for (int i = 0; i < 8; ++i) {
            const int idx = t + i * 256;
            const int row = idx >> 4;
            const int col = (idx & 15) * 4;      // in halves == in floats
            float4 v = xg[idx];
            uint2 hiv;
            hiv.x = packf2(v.x, v.y);
            hiv.y = packf2(v.z, v.w);
            *(uint2*)&Xs[row * XS_STRIDE + col] = hiv;
        }
    }
    // Stage W (64x64 fp32) -> Wsm fp16
    {
        const int d   = t >> 2;
        const int seg = (t & 3) * 16;
        const float4* wg = (const float4*)(W + d * 64 + seg);
        #pragma unroll
        for (int i = 0; i < 4; ++i) {
            float4 v = wg[i];
            uint2 hiv;
            hiv.x = packf2(v.x, v.y);
            hiv.y = packf2(v.z, v.w);
            *(uint2*)&Wsm[d * XS_STRIDE + seg + 4 * i] = hiv;
        }
    }
    __syncthreads();

    const int lane = t & 31, warp = t >> 5;
    const int quad = lane >> 3, l7 = lane & 7;
    const uint32_t sX = (uint32_t)__cvta_generic_to_shared(Xs);
    const uint32_t sW = (uint32_t)__cvta_generic_to_shared(Wsm);

    const int aRow = warp * 16 + ((quad & 1) << 3) + l7;
    const int aK   = (quad >> 1) << 3;
    const int bRow = ((quad >> 1) << 3) + l7;
    const int bK   = (quad & 1) << 3;

    float acc[8][4];
    #pragma unroll
    for (int ni = 0; ni < 8; ++ni)
        #pragma unroll
        for (int j = 0; j < 4; ++j) acc[ni][j] = 0.0f;

    #pragma unroll
    for (int ks = 0; ks < 4; ++ks) {
        const int koff = ks * 16;
        uint32_t a0, a1, a2, a3;
        {
            uint32_t addr = sX + (uint32_t)(aRow * XS_STRIDE + koff + aK) * 2;
            asm volatile(
                "ldmatrix.sync.aligned.m8n8.x4.shared.b16 {%0,%1,%2,%3}, [%4];"
                : "=r"(a0), "=r"(a1), "=r"(a2), "=r"(a3) : "r"(addr));
        }
        uint32_t br[8][2];
        #pragma unroll
        for (int p = 0; p < 4; ++p) {
            uint32_t addr = sW +
                (uint32_t)((p * 16 + bRow) * XS_STRIDE + koff + bK) * 2;
            uint32_t r0, r1, r2, r3;
            asm volatile(
                "ldmatrix.sync.aligned.m8n8.x4.shared.b16 {%0,%1,%2,%3}, [%4];"
                : "=r"(r0), "=r"(r1), "=r"(r2), "=r"(r3) : "r"(addr));
            br[2 * p][0]     = r0; br[2 * p][1]     = r1;
            br[2 * p + 1][0] = r2; br[2 * p + 1][1] = r3;
        }
        #pragma unroll
        for (int ni = 0; ni < 8; ++ni)
            asm volatile(
                "mma.sync.aligned.m16n8k16.row.col.f32.f16.f16.f32 "
                "{%0,%1,%2,%3}, {%4,%5,%6,%7}, {%8,%9}, {%0,%1,%2,%3};"
                : "+f"(acc[ni][0]), "+f"(acc[ni][1]),
                  "+f"(acc[ni][2]), "+f"(acc[ni][3])
                : "r"(a0), "r"(a1), "r"(a2), "r"(a3),
                  "r"(br[ni][0]), "r"(br[ni][1]));
    }

    // Epilogue: bias + tanh_fast + scale -> smem (each warp writes only its
    // own 16 rows of Xs, which it alone read -- no pre-sync needed).
    const int rl0 = warp * 16 + (lane >> 2);     // local row 0..127
    const int cb  = (lane & 3) * 2;

    #pragma unroll
    for (int ni = 0; ni < 8; ++ni) {
        const int c = ni * 8 + cb;
        const float bv0 = bs[c], bv1 = bs[c + 1];

        float v0 = tanh_fast(acc[ni][0] + bv0) * scale;
        float v1 = tanh_fast(acc[ni][1] + bv1) * scale;
        *(uint32_t*)&Xs[rl0 * XS_STRIDE + c] = packf2(v0, v1);

        float v2 = tanh_fast(acc[ni][2] + bv0) * scale;
        float v3 = tanh_fast(acc[ni][3] + bv1) * scale;
        *(uint32_t*)&Xs[(rl0 + 8) * XS_STRIDE + c] = packf2(v2, v3);
    }
    __syncthreads();

    // Coalesced output: 128 rows x 64 halves; 8 threads per row, STG.128.
    #pragma unroll
    for (int p = 0; p < 4; ++p) {
        const int idx = t + p * 256;             // 0..1023
        const int row = idx >> 3;                // 0..127
        const int seg = idx & 7;                 // 16B segment within row
        uint4 v = *(uint4*)&Xs[row * XS_STRIDE + seg * 8];
        const size_t g = (size_t)((b << 10) + bis * 128 + row) * KC + h * 64 + seg * 8;
        *(uint4*)&out[g] = v;
    }
}

// ---------------------------------------------------------------------------
// fp16 NT GEMM: C[b] = A[b] * B[b]^T, M=N=K=1024, 4 batches.
// 128x128 tile, BK=32, 256 threads, mma.sync m16n8k16, 3-stage cp.async.
// ---------------------------------------------------------------------------
__global__ void __launch_bounds__(256, 2)
gemm_fp16_nt(const __half* __restrict__ A,
             const __half* __restrict__ B,
             float* __restrict__ C)
{
    constexpr int BM = 128, BN = 128, BK = 32, LDS = 40, NSTAGE = 3;
    constexpr int KTILES = KC / BK;              // 32
    extern __shared__ __half sh[];

    const int t    = threadIdx.x;
    const int lane = t & 31;
    const int warp = t >> 5;
    const int wm   = warp & 1;
    const int wn   = warp >> 1;
    const int mW   = wm * 64;
    const int nW   = wn * 32;
    const int quad = lane >> 3;
    const int l7   = lane & 7;

    A += (size_t)blockIdx.z * SS * KC + (size_t)blockIdx.y * BM * KC;
    B += (size_t)blockIdx.z * SS * KC + (size_t)blockIdx.x * BN * KC;
    C += (size_t)blockIdx.z * SS * SS;

    const uint32_t sbase = (uint32_t)__cvta_generic_to_shared(sh);
    const uint32_t stageBytes = (uint32_t)(BM + BN) * LDS * 2;
    const uint32_t bOffBytes  = (uint32_t)BM * LDS * 2;

    const int rS = t >> 2;
    const int cS = (t & 3) * 8;
    const __half* gA0 = A + (size_t)rS * KC + cS;
    const __half* gA1 = A + (size_t)(rS + 64) * KC + cS;
    const __half* gB0 = B + (size_t)rS * KC + cS;
    const __half* gB1 = B + (size_t)(rS + 64) * KC + cS;
    const uint32_t dA0 = (uint32_t)(rS * LDS + cS) * 2;
    const uint32_t dA1 = (uint32_t)((rS + 64) * LDS + cS) * 2;

    #define LOAD_STAGE(kt, s)                                                   \
    do {                                                                        \
        uint32_t sb = sbase + (uint32_t)(s) * stageBytes;                       \
        int ko = (kt) * BK;                                                     \
        asm volatile("cp.async.cg.shared.global [%0], [%1], 16;" ::             \
            "r"(sb + dA0), "l"(gA0 + ko));                                      \
        asm volatile("cp.async.cg.shared.global [%0], [%1], 16;" ::             \
            "r"(sb + dA1), "l"(gA1 + ko));                                      \
        asm volatile("cp.async.cg.shared.global [%0], [%1], 16;" ::             \
            "r"(sb + bOffBytes + dA0), "l"(gB0 + ko));                          \
        asm volatile("cp.async.cg.shared.global [%0], [%1], 16;" ::             \
            "r"(sb + bOffBytes + dA1), "l"(gB1 + ko));                          \
    } while (0)

    float acc[4][4][4];
    #pragma unroll
    for (int mi = 0; mi < 4; ++mi)
        #pragma unroll
        for (int ni = 0; ni < 4; ++ni)
            #pragma unroll
            for (int r = 0; r < 4; ++r) acc[mi][ni][r] = 0.0f;

    const int aRow  = mW + ((quad & 1) << 3) + l7;
    const int aKoff = (quad >> 1) << 3;
    const int bRowQ = ((quad >> 1) << 3) + l7;
    const int bKoff = (quad & 1) << 3;

    LOAD_STAGE(0, 0);
    asm volatile("cp.async.commit_group;");
    LOAD_STAGE(1, 1);
    asm volatile("cp.async.commit_group;");
    asm volatile("cp.async.wait_group 1;");
    __syncthreads();

    for (int kt = 0; kt < KTILES; ++kt) {
        if (kt + 2 < KTILES) {
            LOAD_STAGE(kt + 2, (kt + 2) % NSTAGE);
        }
        asm volatile("cp.async.commit_group;");

        const uint32_t sA = sbase + (uint32_t)(kt % NSTAGE) * stageBytes;
        const uint32_t sB = sA + bOffBytes;

        #pragma unroll
        for (int ks = 0; ks < 2; ++ks) {
            uint32_t ar[4][4];
            #pragma unroll
            for (int mi = 0; mi < 4; ++mi) {
                uint32_t addr = sA +
                    (uint32_t)((aRow + mi * 16) * LDS + ks * 16 + aKoff) * 2;
                asm volatile(
                    "ldmatrix.sync.aligned.m8n8.x4.shared.b16 {%0,%1,%2,%3}, [%4];"
                    : "=r"(ar[mi][0]), "=r"(ar[mi][1]),
                      "=r"(ar[mi][2]), "=r"(ar[mi][3])
                    : "r"(addr));
            }
            uint32_t br[4][2];
            #pragma unroll
            for (int p = 0; p < 2; ++p) {
                uint32_t addr = sB +
                    (uint32_t)((nW + p * 16 + bRowQ) * LDS + ks * 16 + bKoff) * 2;
                uint32_t r0, r1, r2, r3;
                asm volatile(
                    "ldmatrix.sync.aligned.m8n8.x4.shared.b16 {%0,%1,%2,%3}, [%4];"
                    : "=r"(r0), "=r"(r1), "=r"(r2), "=r"(r3)
                    : "r"(addr));
                br[2 * p][0]     = r0; br[2 * p][1]     = r1;
                br[2 * p + 1][0] = r2; br[2 * p + 1][1] = r3;
            }
            #pragma unroll
            for (int mi = 0; mi < 4; ++mi)
                #pragma unroll
                for (int ni = 0; ni < 4; ++ni)
                    asm volatile(
                        "mma.sync.aligned.m16n8k16.row.col.f32.f16.f16.f32 "
                        "{%0,%1,%2,%3}, {%4,%5,%6,%7}, {%8,%9}, {%0,%1,%2,%3};"
                        : "+f"(acc[mi][ni][0]), "+f"(acc[mi][ni][1]),
                          "+f"(acc[mi][ni][2]), "+f"(acc[mi][ni][3])
                        : "r"(ar[mi][0]), "r"(ar[mi][1]),
                          "r"(ar[mi][2]), "r"(ar[mi][3]),
                          "r"(br[ni][0]), "r"(br[ni][1]));
        }

        asm volatile("cp.async.wait_group 1;");
        __syncthreads();
    }

    #pragma unroll
    for (int mi = 0; mi < 4; ++mi) {
        #pragma unroll
        for (int ni = 0; ni < 4; ++ni) {
            int row = blockIdx.y * BM + mW + mi * 16 + (lane >> 2);
            int col = blockIdx.x * BN + nW + ni * 8 + ((lane & 3) << 1);
            float2 v0 = make_float2(acc[mi][ni][0], acc[mi][ni][1]);
            float2 v1 = make_float2(acc[mi][ni][2], acc[mi][ni][3]);
            *(float2*)&C[(size_t)row * SS + col]       = v0;
            *(float2*)&C[(size_t)(row + 8) * SS + col] = v1;
        }
    }
    #undef LOAD_STAGE
}

// ---------------------------------------------------------------------------
// Masked softmax over rows of 1024, in-place on C (= d_out).
// ---------------------------------------------------------------------------
__global__ void __launch_bounds__(256)
softmax_kernel(float* __restrict__ C, const int* __restrict__ mask,
               const float* __restrict__ bcp)
{
    const size_t row = blockIdx.x;
    float* p = C + row * 1024;
    const int* mp = mask + row * 1024;
    const int t = threadIdx.x;
    const float bias = bcp[0];

    float4 v = ((const float4*)p)[t];
    int4  mk = ((const int4*)mp)[t];

    float x0 = mk.x ? v.x + bias : NEGV;
    float x1 = mk.y ? v.y + bias : NEGV;
    float x2 = mk.z ? v.z + bias : NEGV;
    float x3 = mk.w ? v.w + bias : NEGV;

    float mx = fmaxf(fmaxf(x0, x1), fmaxf(x2, x3));
    #pragma unroll
    for (int o = 16; o; o >>= 1)
        mx = fmaxf(mx, __shfl_xor_sync(0xffffffffu, mx, o));

    __shared__ float red_m[8];
    __shared__ float red_s[8];
    if ((t & 31) == 0) red_m[t >> 5] = mx;
    __syncthreads();
    mx = red_m[0];
    #pragma unroll
    for (int i = 1; i < 8; ++i) mx = fmaxf(mx, red_m[i]);

    float e0 = __expf(x0 - mx);
    float e1 = __expf(x1 - mx);
    float e2 = __expf(x2 - mx);
    float e3 = __expf(x3 - mx);
    float s = e0 + e1 + e2 + e3;
    #pragma unroll
    for (int o = 16; o; o >>= 1)
        s += __shfl_xor_sync(0xffffffffu, s, o);
    if ((t & 31) == 0) red_s[t >> 5] = s;
    __syncthreads();
    float tot = red_s[0];
    #pragma unroll
    for (int i = 1; i < 8; ++i) tot += red_s[i];

    const float inv = __fdividef(1.0f, tot);
    v.x = e0 * inv; v.y = e1 * inv; v.z = e2 * inv; v.w = e3 * inv;
    ((float4*)p)[t] = v;
}

// ---------------------------------------------------------------------------
// Launch
// ---------------------------------------------------------------------------
extern "C" void kernel_launch(void* const* d_in, const int* in_sizes, int n_in,
                              void* d_out, int out_size)
{
    const float* query = (const float*)d_in[0];
    const float* key   = (const float*)d_in[1];
    const int*   mask  = (const int*)  d_in[2];
    const float* Wq    = (const float*)d_in[3];
    const float* bq    = (const float*)d_in[4];
    const float* Wk    = (const float*)d_in[5];
    const float* bk    = (const float*)d_in[6];
    const float* Wc    = (const float*)d_in[7];
    const float* bc    = (const float*)d_in[8];
    float* out = (float*)d_out;

    __half *qc, *kc;
    cudaGetSymbolAddress((void**)&qc, g_Qc);
    cudaGetSymbolAddress((void**)&kc, g_Kc);

    const int smemBytes = 3 * (128 + 128) * 40 * 2;   // 61440
    cudaFuncSetAttribute(gemm_fp16_nt,
                         cudaFuncAttributeMaxDynamicSharedMemorySize, smemBytes);
    cudaFuncSetAttribute(proj_mma_kernel,
                         cudaFuncAttributeMaxDynamicSharedMemorySize, PROJ_SMEM);

    // Tensor-core projection (pure fp16): Q and K -> fp16 slabs (stride 1024)
    proj_mma_kernel<<<1024, 256, PROJ_SMEM>>>(query, key, Wq, bq, Wk, bk, Wc,
                                              qc, kc);

    // comb[b] = Qc[b] @ Kc[b]^T  (K=1024)
    gemm_fp16_nt<<<dim3(8, 8, 4), 256, smemBytes>>>(qc, kc, out);

    // mask + softmax, in-place
    softmax_kernel<<<BB * SS, 256>>>(out, mask, bc);
}